// round 14
// baseline (speedup 1.0000x reference)
#include <cuda_runtime.h>
#include <cuda_fp16.h>
#include <cstdint>
#include <math.h>

#define T_TOK 2048
#define DDIM  1024
#define NEXP  64
#define TOPK  8
#define FDIM  768
#define CAP   512

// -------------------- device scratch --------------------
__device__ int    g_cnt[NEXP];
__device__ int    g_slot_tok[NEXP * CAP];
__device__ float  g_slot_w[NEXP * CAP];
__device__ __half g_H[(size_t)NEXP * CAP * FDIM];        // ~50 MB
__device__ __half g_shared_h[(size_t)T_TOK * FDIM];      // ~3 MB

// -------------------- helpers --------------------
__device__ __forceinline__ uint32_t pack_h2(float a, float b) {
    __half2 h = __floats2half2_rn(a, b);
    return *reinterpret_cast<uint32_t*>(&h);
}

__device__ __forceinline__ void mma16(float c[4], const uint32_t a[4],
                                      uint32_t b0, uint32_t b1) {
    asm volatile(
        "mma.sync.aligned.m16n8k16.row.col.f32.f16.f16.f32 "
        "{%0,%1,%2,%3},{%4,%5,%6,%7},{%8,%9},{%0,%1,%2,%3};\n"
        : "+f"(c[0]), "+f"(c[1]), "+f"(c[2]), "+f"(c[3])
        : "r"(a[0]), "r"(a[1]), "r"(a[2]), "r"(a[3]), "r"(b0), "r"(b1));
}

// ldmatrix x4: loads a0..a3 of an m16k16 fp16 A fragment in one instruction.
__device__ __forceinline__ void ldmA(uint32_t a[4], uint32_t addr) {
    asm volatile("ldmatrix.sync.aligned.m8n8.x4.shared.b16 {%0,%1,%2,%3}, [%4];"
        : "=r"(a[0]), "=r"(a[1]), "=r"(a[2]), "=r"(a[3]) : "r"(addr));
}

// -------------------- counters reset --------------------
__global__ void zero_cnt_kernel() {
    if (threadIdx.x < NEXP) g_cnt[threadIdx.x] = 0;
}

// -------------------- router --------------------
__global__ __launch_bounds__(256)
void router_kernel(const float* __restrict__ X, const float* __restrict__ RW) {
    __shared__ float xs[32][68];
    __shared__ float rws[64][68];
    __shared__ float probs[32][65];

    const int tid = threadIdx.x;
    const int t0  = blockIdx.x * 32;
    const int t   = tid >> 3;
    const int el  = tid & 7;

    float acc[8] = {0.f,0.f,0.f,0.f,0.f,0.f,0.f,0.f};

    for (int kc = 0; kc < DDIM; kc += 64) {
        #pragma unroll
        for (int i = 0; i < 2; i++) {
            int idx = tid + i * 256;
            int row = idx >> 4, c4 = idx & 15;
            *reinterpret_cast<float4*>(&xs[row][c4 * 4]) =
                *reinterpret_cast<const float4*>(X + (size_t)(t0 + row) * DDIM + kc + c4 * 4);
        }
        #pragma unroll
        for (int i = 0; i < 4; i++) {
            int idx = tid + i * 256;
            int row = idx >> 4, c4 = idx & 15;
            *reinterpret_cast<float4*>(&rws[row][c4 * 4]) =
                *reinterpret_cast<const float4*>(RW + (size_t)row * DDIM + kc + c4 * 4);
        }
        __syncthreads();
        for (int k = 0; k < 64; k++) {
            float xv = xs[t][k];
            #pragma unroll
            for (int j = 0; j < 8; j++) acc[j] += xv * rws[el + 8 * j][k];
        }
        __syncthreads();
    }

    float mx = acc[0];
    #pragma unroll
    for (int j = 1; j < 8; j++) mx = fmaxf(mx, acc[j]);
    #pragma unroll
    for (int m = 1; m < 8; m <<= 1) mx = fmaxf(mx, __shfl_xor_sync(0xffffffffu, mx, m));
    float p[8], s = 0.f;
    #pragma unroll
    for (int j = 0; j < 8; j++) { p[j] = expf(acc[j] - mx); s += p[j]; }
    #pragma unroll
    for (int m = 1; m < 8; m <<= 1) s += __shfl_xor_sync(0xffffffffu, s, m);
    float inv = 1.f / s;
    #pragma unroll
    for (int j = 0; j < 8; j++) probs[t][el + 8 * j] = p[j] * inv;
    __syncthreads();

    if (tid < 32) {
        const int token = t0 + tid;
        float tw[TOPK]; int te[TOPK];
        float psum = 0.f;
        #pragma unroll
        for (int k = 0; k < TOPK; k++) {
            float best = -1.f; int be = 0;
            for (int e2 = 0; e2 < NEXP; e2++) {
                float v = probs[tid][e2];
                if (v > best) { best = v; be = e2; }
            }
            probs[tid][be] = -2.f;
            tw[k] = best; te[k] = be; psum += best;
        }
        float invp = 1.f / psum;
        #pragma unroll
        for (int k = 0; k < TOPK; k++) {
            int pos = atomicAdd(&g_cnt[te[k]], 1);
            if (pos < CAP) {
                g_slot_tok[te[k] * CAP + pos] = token;
                g_slot_w[te[k] * CAP + pos]   = tw[k] * invp;
            }
        }
    }
}

// smem word layouts (uint32 words):
//   A   [m][k2]     stride 36  : 128 x (32 + 4 pad) = 4608 words (K=64 fp16 pairs)
//   Bgu [k2][n][2]  stride 280 : 32 k-pair rows x (256 data + 24 pad) = 8960 words
//       word k2*280 + n*2 + {0:gate, 1:up}.  Fragment pair = one LDS.64.
//   B   [k2][n]     stride 136 : down kernel (single matrix), 4352 words

// ==================== fused gate/up GEMM + SiLU (fp16, ldmatrix + LDS.64) ====================
// BM=128, BN=128, BK=64, 512 threads (16 warps 4x4, 32x32 warp tile, dual acc).
// buffer = A 4608 + Bgu 8960 = 13568 words; x2 = 108544 B.
template<bool EXPERT>
__global__ __launch_bounds__(512)
void gateup_kernel(const float* __restrict__ X, const float* __restrict__ WG,
                   const float* __restrict__ WU, int ldb) {
    extern __shared__ uint32_t smem[];
    uint32_t* bufs = smem;
    int* s_tok = (int*)(smem + 2 * 13568);

    const int tid = threadIdx.x;
    const int e  = EXPERT ? blockIdx.z : 0;
    const int ne = EXPERT ? min(g_cnt[e], CAP) : T_TOK;
    const int m0 = blockIdx.y * 128;
    if (m0 >= ne) return;
    const int n0 = blockIdx.x * 128;

    const float* Bg = EXPERT ? (WG + (size_t)e * DDIM * FDIM) : WG;
    const float* Bu = EXPERT ? (WU + (size_t)e * DDIM * FDIM) : WU;

    if (EXPERT) {
        for (int i = tid; i < 128; i += 512) {
            int m = m0 + i;
            s_tok[i] = (m < ne) ? g_slot_tok[e * CAP + m] : 0;
        }
        __syncthreads();
    }

    // A producer: unit idx = tid + i*512 -> m = idx>>3, s = idx&7
    const float* rpA[2];
    int am[2], as_[2];
    #pragma unroll
    for (int i = 0; i < 2; i++) {
        int idx = tid + i * 512;
        am[i] = idx >> 3; as_[i] = idx & 7;
        rpA[i] = (EXPERT ? (X + (size_t)s_tok[am[i]] * DDIM)
                         : (X + (size_t)(m0 + am[i]) * DDIM)) + as_[i] * 8;
    }
    // B producer: unit idx -> kp = idx>>5, ng = idx&31 (4-n group)
    int bkp[2], bo[2];
    uint32_t bwu[2];   // uint4 index into Bgu
    #pragma unroll
    for (int i = 0; i < 2; i++) {
        int idx = tid + i * 512;
        bkp[i] = idx >> 5;
        bo[i]  = n0 + (idx & 31) * 4;
        bwu[i] = bkp[i] * 70 + (idx & 31) * 2;
    }

    const int lane = tid & 31, warp = tid >> 5;
    const int wm = (warp >> 2) * 32, wn = (warp & 3) * 32;
    const int g = lane >> 2, tig = lane & 3;

    // ldmatrix per-lane A row offset (words): rows wm+(lane&15), halves by lane>>4
    const uint32_t sbase = (uint32_t)__cvta_generic_to_shared(smem);
    const int alane = (wm + (lane & 15)) * 36 + (lane >> 4) * 4;

    float cG[2][4][4] = {};
    float cU[2][4][4] = {};

    float4 hA[4], hg0, hg1, hu0, hu1;

    // ---- prologue: full tile 0 ----
    {
        uint32_t* sA  = bufs;
        uint4* sBgu = reinterpret_cast<uint4*>(bufs + 4608);
        #pragma unroll
        for (int i = 0; i < 2; i++) {
            float4 v0 = *reinterpret_cast<const float4*>(rpA[i]);
            float4 v1 = *reinterpret_cast<const float4*>(rpA[i] + 4);
            uint4 w = { pack_h2(v0.x, v0.y), pack_h2(v0.z, v0.w),
                        pack_h2(v1.x, v1.y), pack_h2(v1.z, v1.w) };
            *reinterpret_cast<uint4*>(sA + am[i] * 36 + as_[i] * 4) = w;
        }
        #pragma unroll
        for (int i = 0; i < 2; i++) {
            const float* pg = Bg + (size_t)(2 * bkp[i]) * ldb + bo[i];
            const float* pu = Bu + (size_t)(2 * bkp[i]) * ldb + bo[i];
            float4 r0 = *reinterpret_cast<const float4*>(pg);
            float4 r1 = *reinterpret_cast<const float4*>(pg + ldb);
            float4 u0 = *reinterpret_cast<const float4*>(pu);
            float4 u1 = *reinterpret_cast<const float4*>(pu + ldb);
            uint4 w0 = { pack_h2(r0.x, r1.x), pack_h2(u0.x, u1.x),
                         pack_h2(r0.y, r1.y), pack_h2(u0.y, u1.y) };
            uint4 w1 = { pack_h2(r0.z, r1.z), pack_h2(u0.z, u1.z),
                         pack_h2(r0.w, r1.w), pack_h2(u0.w, u1.w) };
            sBgu[bwu[i]]     = w0;
            sBgu[bwu[i] + 1] = w1;
        }
    }
    __syncthreads();

    const int NK = DDIM / 64;
    for (int kt = 0; kt < NK; kt++) {
        const bool more = (kt + 1 < NK);
        const int k1 = (kt + 1) * 64;
        const uint32_t bufw = (kt & 1) * 13568;
        const uint32_t aAddr = sbase + 4 * (bufw + alane);
        const uint2* uBgu = reinterpret_cast<const uint2*>(bufs + bufw + 4608);
        uint32_t* nA  = bufs + ((kt + 1) & 1) * 13568;
        uint4* nBgu = reinterpret_cast<uint4*>(nA + 4608);

        // prefetch A (both units) + B unit 0 of next tile
        if (more) {
            #pragma unroll
            for (int i = 0; i < 2; i++) {
                hA[2 * i]     = *reinterpret_cast<const float4*>(rpA[i] + k1);
                hA[2 * i + 1] = *reinterpret_cast<const float4*>(rpA[i] + k1 + 4);
            }
            const float* pg = Bg + (size_t)(k1 + 2 * bkp[0]) * ldb + bo[0];
            const float* pu = Bu + (size_t)(k1 + 2 * bkp[0]) * ldb + bo[0];
            hg0 = *reinterpret_cast<const float4*>(pg);
            hg1 = *reinterpret_cast<const float4*>(pg + ldb);
            hu0 = *reinterpret_cast<const float4*>(pu);
            hu1 = *reinterpret_cast<const float4*>(pu + ldb);
        }

        // compute ks = 0,1
        #pragma unroll
        for (int ks = 0; ks < 2; ks++) {
            int ko = ks * 8;
            uint32_t a[2][4];
            ldmA(a[0], aAddr + 4 * ko);
            ldmA(a[1], aAddr + 4 * (576 + ko));
            #pragma unroll
            for (int nf = 0; nf < 4; nf++) {
                int cn = wn + nf * 8 + g;
                uint2 b0 = uBgu[(ko + tig) * 140 + cn];
                uint2 b1 = uBgu[(ko + tig + 4) * 140 + cn];
                mma16(cG[0][nf], a[0], b0.x, b1.x);
                mma16(cG[1][nf], a[1], b0.x, b1.x);
                mma16(cU[0][nf], a[0], b0.y, b1.y);
                mma16(cU[1][nf], a[1], b0.y, b1.y);
            }
        }

        // store A + B unit0; prefetch B unit1
        if (more) {
            #pragma unroll
            for (int i = 0; i < 2; i++) {
                uint4 w = { pack_h2(hA[2*i].x, hA[2*i].y), pack_h2(hA[2*i].z, hA[2*i].w),
                            pack_h2(hA[2*i+1].x, hA[2*i+1].y), pack_h2(hA[2*i+1].z, hA[2*i+1].w) };
                *reinterpret_cast<uint4*>(nA + am[i] * 36 + as_[i] * 4) = w;
            }
            {
                uint4 w0 = { pack_h2(hg0.x, hg1.x), pack_h2(hu0.x, hu1.x),
                             pack_h2(hg0.y, hg1.y), pack_h2(hu0.y, hu1.y) };
                uint4 w1 = { pack_h2(hg0.z, hg1.z), pack_h2(hu0.z, hu1.z),
                             pack_h2(hg0.w, hg1.w), pack_h2(hu0.w, hu1.w) };
                nBgu[bwu[0]]     = w0;
                nBgu[bwu[0] + 1] = w1;
            }
            const float* pg = Bg + (size_t)(k1 + 2 * bkp[1]) * ldb + bo[1];
            const float* pu = Bu + (size_t)(k1 + 2 * bkp[1]) * ldb + bo[1];
            hg0 = *reinterpret_cast<const float4*>(pg);
            hg1 = *reinterpret_cast<const float4*>(pg + ldb);
            hu0 = *reinterpret_cast<const float4*>(pu);
            hu1 = *reinterpret_cast<const float4*>(pu + ldb);
        }

        // compute ks = 2,3
        #pragma unroll
        for (int ks = 2; ks < 4; ks++) {
            int ko = ks * 8;
            uint32_t a[2][4];
            ldmA(a[0], aAddr + 4 * ko);
            ldmA(a[1], aAddr + 4 * (576 + ko));
            #pragma unroll
            for (int nf = 0; nf < 4; nf++) {
                int cn = wn + nf * 8 + g;
                uint2 b0 = uBgu[(ko + tig) * 140 + cn];
                uint2 b1 = uBgu[(ko + tig + 4) * 140 + cn];
                mma16(cG[0][nf], a[0], b0.x, b1.x);
                mma16(cG[1][nf], a[1], b0.x, b1.x);
                mma16(cU[0][nf], a[0], b0.y, b1.y);
                mma16(cU[1][nf], a[1], b0.y, b1.y);
            }
        }

        // store B unit1
        if (more) {
            uint4 w0 = { pack_h2(hg0.x, hg1.x), pack_h2(hu0.x, hu1.x),
                         pack_h2(hg0.y, hg1.y), pack_h2(hu0.y, hu1.y) };
            uint4 w1 = { pack_h2(hg0.z, hg1.z), pack_h2(hu0.z, hu1.z),
                         pack_h2(hg0.w, hg1.w), pack_h2(hu0.w, hu1.w) };
            nBgu[bwu[1]]     = w0;
            nBgu[bwu[1] + 1] = w1;
        }
        __syncthreads();
    }

    __half* Hbase = EXPERT ? (g_H + (size_t)e * CAP * FDIM) : g_shared_h;
    #pragma unroll
    for (int mf = 0; mf < 2; mf++)
        #pragma unroll
        for (int nf = 0; nf < 4; nf++)
            #pragma unroll
            for (int half_ = 0; half_ < 2; half_++) {
                int row = wm + mf * 16 + g + half_ * 8;
                int col = wn + nf * 8 + 2 * tig;
                int m = m0 + row;
                if (m < ne) {
                    float g0 = cG[mf][nf][half_ * 2],     u0 = cU[mf][nf][half_ * 2];
                    float g1 = cG[mf][nf][half_ * 2 + 1], u1 = cU[mf][nf][half_ * 2 + 1];
                    float h0 = g0 / (1.f + expf(-g0)) * u0;
                    float h1 = g1 / (1.f + expf(-g1)) * u1;
                    *reinterpret_cast<uint32_t*>(Hbase + (size_t)m * FDIM + n0 + col) =
                        pack_h2(h0, h1);
                }
            }
}

// ==================== down GEMM (fp16, ldmatrix A) ====================
// BM=128, BN=128, BK=64, 512 threads. K = 768 -> 12 k-tiles.
// buffer = A 4608 + B 4352 = 8960 words; x2 = 70 KB.
template<bool EXPERT>
__global__ __launch_bounds__(512)
void down_kernel(const float* __restrict__ WD, float* __restrict__ out) {
    extern __shared__ uint32_t smem[];
    uint32_t* bufs = smem;
    int* s_tok = (int*)(smem + 2 * 8960);
    float* s_w = (float*)(s_tok + 128);

    const int tid = threadIdx.x;
    const int e  = EXPERT ? blockIdx.z : 0;
    const int ne = EXPERT ? min(g_cnt[e], CAP) : T_TOK;
    const int m0 = blockIdx.y * 128;
    if (m0 >= ne) return;
    const int n0 = blockIdx.x * 128;

    const float* B = EXPERT ? (WD + (size_t)e * FDIM * DDIM) : WD;
    const __half* Abase = EXPERT ? (g_H + (size_t)e * CAP * FDIM) : g_shared_h;

    if (EXPERT) {
        for (int i = tid; i < 128; i += 512) {
            int m = m0 + i;
            s_tok[i] = (m < ne) ? g_slot_tok[e * CAP + m] : 0;
            s_w[i]   = (m < ne) ? g_slot_w[e * CAP + m] : 0.f;
        }
        __syncthreads();
    }

    // A producer (fp16 passthrough)
    const __half* rpA[2];
    int am[2], as_[2];
    #pragma unroll
    for (int i = 0; i < 2; i++) {
        int idx = tid + i * 512;
        am[i] = idx >> 3; as_[i] = idx & 7;
        rpA[i] = Abase + (size_t)(m0 + am[i]) * FDIM + as_[i] * 8;
    }
    int bkp[2], bo[2], bw_[2];
    #pragma unroll
    for (int i = 0; i < 2; i++) {
        int idx = tid + i * 512;
        bkp[i] = idx >> 5;
        bo[i]  = n0 + (idx & 31) * 4;
        bw_[i] = bkp[i] * 136 + (idx & 31) * 4;
    }

    const int lane = tid & 31, warp = tid >> 5;
    const int wm = (warp >> 2) * 32, wn = (warp & 3) * 32;
    const int g = lane >> 2, tig = lane & 3;

    const uint32_t sbase = (uint32_t)__cvta_generic_to_shared(smem);
    const int alane = (wm + (lane & 15)) * 36 + (lane >> 4) * 4;

    float c[2][4][4] = {};
    uint4 hA[2];
    float4 hb0, hb1;

    // ---- prologue: full tile 0 ----
    {
        uint32_t* sA = bufs;
        uint32_t* sB = sA + 4608;
        #pragma unroll
        for (int i = 0; i < 2; i++) {
            uint4 w = *reinterpret_cast<const uint4*>(rpA[i]);
            *reinterpret_cast<uint4*>(sA + am[i] * 36 + as_[i] * 4) = w;
        }
        #pragma unroll
        for (int i = 0; i < 2; i++) {
            const float* pb = B + (size_t)(2 * bkp[i]) * DDIM + bo[i];
            float4 r0 = *reinterpret_cast<const float4*>(pb);
            float4 r1 = *reinterpret_cast<const float4*>(pb + DDIM);
            uint4 w = { pack_h2(r0.x, r1.x), pack_h2(r0.y, r1.y),
                        pack_h2(r0.z, r1.z), pack_h2(r0.w, r1.w) };
            *reinterpret_cast<uint4*>(sB + bw_[i]) = w;
        }
    }
    __syncthreads();

    const int NK = FDIM / 64;
    for (int kt = 0; kt < NK; kt++) {
        const bool more = (kt + 1 < NK);
        const int k1 = (kt + 1) * 64;
        const uint32_t bufw = (kt & 1) * 8960;
        const uint32_t aAddr = sbase + 4 * (bufw + alane);
        const uint32_t* uB = bufs + bufw + 4608;
        uint32_t* nA = bufs + ((kt + 1) & 1) * 8960;
        uint32_t* nB = nA + 4608;

        if (more) {
            #pragma unroll
            for (int i = 0; i < 2; i++)
                hA[i] = *reinterpret_cast<const uint4*>(rpA[i] + k1);
            const float* pb = B + (size_t)(k1 + 2 * bkp[0]) * DDIM + bo[0];
            hb0 = *reinterpret_cast<const float4*>(pb);
            hb1 = *reinterpret_cast<const float4*>(pb + DDIM);
        }

        #pragma unroll
        for (int ks = 0; ks < 2; ks++) {
            int ko = ks * 8;
            uint32_t a[2][4];
            ldmA(a[0], aAddr + 4 * ko);
            ldmA(a[1], aAddr + 4 * (576 + ko));
            #pragma unroll
            for (int nf = 0; nf < 4; nf++) {
                int cn = wn + nf * 8 + g;
                uint32_t b0 = uB[(ko + tig) * 136 + cn];
                uint32_t b1 = uB[(ko + tig + 4) * 136 + cn];
                mma16(c[0][nf], a[0], b0, b1);
                mma16(c[1][nf], a[1], b0, b1);
            }
        }

        if (more) {
            #pragma unroll
            for (int i = 0; i < 2; i++)
                *reinterpret_cast<uint4*>(nA + am[i] * 36 + as_[i] * 4) = hA[i];
            uint4 w = { pack_h2(hb0.x, hb1.x), pack_h2(hb0.y, hb1.y),
                        pack_h2(hb0.z, hb1.z), pack_h2(hb0.w, hb1.w) };
            *reinterpret_cast<uint4*>(nB + bw_[0]) = w;
            const float* pb = B + (size_t)(k1 + 2 * bkp[1]) * DDIM + bo[1];
            hb0 = *reinterpret_cast<const float4*>(pb);
            hb1 = *reinterpret_cast<const float4*>(pb + DDIM);
        }

        #pragma unroll
        for (int ks = 2; ks < 4; ks++) {
            int ko = ks * 8;
            uint32_t a[2][4];
            ldmA(a[0], aAddr + 4 * ko);
            ldmA(a[1], aAddr + 4 * (576 + ko));
            #pragma unroll
            for (int nf = 0; nf < 4; nf++) {
                int cn = wn + nf * 8 + g;
                uint32_t b0 = uB[(ko + tig) * 136 + cn];
                uint32_t b1 = uB[(ko + tig + 4) * 136 + cn];
                mma16(c[0][nf], a[0], b0, b1);
                mma16(c[1][nf], a[1], b0, b1);
            }
        }

        if (more) {
            uint4 w = { pack_h2(hb0.x, hb1.x), pack_h2(hb0.y, hb1.y),
                        pack_h2(hb0.z, hb1.z), pack_h2(hb0.w, hb1.w) };
            *reinterpret_cast<uint4*>(nB + bw_[1]) = w;
        }
        __syncthreads();
    }

    #pragma unroll
    for (int mf = 0; mf < 2; mf++)
        #pragma unroll
        for (int nf = 0; nf < 4; nf++)
            #pragma unroll
            for (int half_ = 0; half_ < 2; half_++) {
                int row = wm + mf * 16 + g + half_ * 8;
                int col = wn + nf * 8 + 2 * tig;
                int m = m0 + row;
                if (m < ne) {
                    float v0 = c[mf][nf][half_ * 2];
                    float v1 = c[mf][nf][half_ * 2 + 1];
                    if (EXPERT) {
                        float w = s_w[row];
                        float* p = out + (size_t)s_tok[row] * DDIM + n0 + col;
                        asm volatile("red.global.add.v2.f32 [%0], {%1,%2};"
                                     :: "l"(p), "f"(v0 * w), "f"(v1 * w) : "memory");
                    } else {
                        float2* p = (float2*)(out + (size_t)m * DDIM + n0 + col);
                        *p = make_float2(v0, v1);
                    }
                }
            }
}

// -------------------- launch --------------------
extern "C" void kernel_launch(void* const* d_in, const int* in_sizes, int n_in,
                              void* d_out, int out_size) {
    const float* X   = (const float*)d_in[0];   // (B,S,D)
    const float* RW  = (const float*)d_in[1];   // (E,D)
    const float* WG  = (const float*)d_in[2];   // (E,D,F)
    const float* WU  = (const float*)d_in[3];   // (E,D,F)
    const float* WD  = (const float*)d_in[4];   // (E,F,D)
    const float* WSG = (const float*)d_in[5];   // (D, 2*SF)
    const float* WSD = (const float*)d_in[6];   // (SF, D)
    float* out = (float*)d_out;

    const int GUSM = (2 * 13568) * 4 + 128 * 4;   // 109056
    const int DSM  = (2 * 8960) * 4 + 128 * 8;    // 72704

    cudaFuncSetAttribute(gateup_kernel<false>, cudaFuncAttributeMaxDynamicSharedMemorySize, GUSM);
    cudaFuncSetAttribute(gateup_kernel<true>,  cudaFuncAttributeMaxDynamicSharedMemorySize, GUSM);
    cudaFuncSetAttribute(down_kernel<false>,   cudaFuncAttributeMaxDynamicSharedMemorySize, DSM);
    cudaFuncSetAttribute(down_kernel<true>,    cudaFuncAttributeMaxDynamicSharedMemorySize, DSM);

    zero_cnt_kernel<<<1, 64>>>();
    router_kernel<<<T_TOK / 32, 256>>>(X, RW);

    // shared expert gate/up: gate cols [0,768), up cols [768,1536)
    gateup_kernel<false><<<dim3(FDIM / 128, T_TOK / 128, 1), 512, GUSM>>>(X, WSG, WSG + FDIM, 2 * FDIM);
    // routed experts gate/up
    gateup_kernel<true><<<dim3(FDIM / 128, CAP / 128, NEXP), 512, GUSM>>>(X, WG, WU, FDIM);

    // shared expert down (initializes every element of out)
    down_kernel<false><<<dim3(DDIM / 128, T_TOK / 128, 1), 512, DSM>>>(WSD, out);
    // routed experts down (weighted atomic scatter)
    down_kernel<true><<<dim3(DDIM / 128, CAP / 128, NEXP), 512, DSM>>>(WD, out);
}

// round 15
// speedup vs baseline: 1.2168x; 1.2168x over previous
#include <cuda_runtime.h>
#include <cuda_fp16.h>
#include <cstdint>
#include <math.h>

#define T_TOK 2048
#define DDIM  1024
#define NEXP  64
#define TOPK  8
#define FDIM  768
#define CAP   512

// -------------------- device scratch --------------------
__device__ int    g_cnt[NEXP];
__device__ int    g_slot_tok[NEXP * CAP];
__device__ float  g_slot_w[NEXP * CAP];
__device__ __half g_H[(size_t)NEXP * CAP * FDIM];        // ~50 MB
__device__ __half g_shared_h[(size_t)T_TOK * FDIM];      // ~3 MB

// -------------------- helpers --------------------
__device__ __forceinline__ uint32_t pack_h2(float a, float b) {
    __half2 h = __floats2half2_rn(a, b);
    return *reinterpret_cast<uint32_t*>(&h);
}

__device__ __forceinline__ void mma16(float c[4], const uint32_t a[4],
                                      uint32_t b0, uint32_t b1) {
    asm volatile(
        "mma.sync.aligned.m16n8k16.row.col.f32.f16.f16.f32 "
        "{%0,%1,%2,%3},{%4,%5,%6,%7},{%8,%9},{%0,%1,%2,%3};\n"
        : "+f"(c[0]), "+f"(c[1]), "+f"(c[2]), "+f"(c[3])
        : "r"(a[0]), "r"(a[1]), "r"(a[2]), "r"(a[3]), "r"(b0), "r"(b1));
}

// -------------------- counters reset --------------------
__global__ void zero_cnt_kernel() {
    if (threadIdx.x < NEXP) g_cnt[threadIdx.x] = 0;
}

// -------------------- router --------------------
__global__ __launch_bounds__(256)
void router_kernel(const float* __restrict__ X, const float* __restrict__ RW) {
    __shared__ float xs[32][68];
    __shared__ float rws[64][68];
    __shared__ float probs[32][65];

    const int tid = threadIdx.x;
    const int t0  = blockIdx.x * 32;
    const int t   = tid >> 3;
    const int el  = tid & 7;

    float acc[8] = {0.f,0.f,0.f,0.f,0.f,0.f,0.f,0.f};

    for (int kc = 0; kc < DDIM; kc += 64) {
        #pragma unroll
        for (int i = 0; i < 2; i++) {
            int idx = tid + i * 256;
            int row = idx >> 4, c4 = idx & 15;
            *reinterpret_cast<float4*>(&xs[row][c4 * 4]) =
                *reinterpret_cast<const float4*>(X + (size_t)(t0 + row) * DDIM + kc + c4 * 4);
        }
        #pragma unroll
        for (int i = 0; i < 4; i++) {
            int idx = tid + i * 256;
            int row = idx >> 4, c4 = idx & 15;
            *reinterpret_cast<float4*>(&rws[row][c4 * 4]) =
                *reinterpret_cast<const float4*>(RW + (size_t)row * DDIM + kc + c4 * 4);
        }
        __syncthreads();
        for (int k = 0; k < 64; k++) {
            float xv = xs[t][k];
            #pragma unroll
            for (int j = 0; j < 8; j++) acc[j] += xv * rws[el + 8 * j][k];
        }
        __syncthreads();
    }

    float mx = acc[0];
    #pragma unroll
    for (int j = 1; j < 8; j++) mx = fmaxf(mx, acc[j]);
    #pragma unroll
    for (int m = 1; m < 8; m <<= 1) mx = fmaxf(mx, __shfl_xor_sync(0xffffffffu, mx, m));
    float p[8], s = 0.f;
    #pragma unroll
    for (int j = 0; j < 8; j++) { p[j] = expf(acc[j] - mx); s += p[j]; }
    #pragma unroll
    for (int m = 1; m < 8; m <<= 1) s += __shfl_xor_sync(0xffffffffu, s, m);
    float inv = 1.f / s;
    #pragma unroll
    for (int j = 0; j < 8; j++) probs[t][el + 8 * j] = p[j] * inv;
    __syncthreads();

    if (tid < 32) {
        const int token = t0 + tid;
        float tw[TOPK]; int te[TOPK];
        float psum = 0.f;
        #pragma unroll
        for (int k = 0; k < TOPK; k++) {
            float best = -1.f; int be = 0;
            for (int e2 = 0; e2 < NEXP; e2++) {
                float v = probs[tid][e2];
                if (v > best) { best = v; be = e2; }
            }
            probs[tid][be] = -2.f;
            tw[k] = best; te[k] = be; psum += best;
        }
        float invp = 1.f / psum;
        #pragma unroll
        for (int k = 0; k < TOPK; k++) {
            int pos = atomicAdd(&g_cnt[te[k]], 1);
            if (pos < CAP) {
                g_slot_tok[te[k] * CAP + pos] = token;
                g_slot_w[te[k] * CAP + pos]   = tw[k] * invp;
            }
        }
    }
}

// smem word layouts (uint32 words):
//   A  [m][k2]  stride 36 : 128 rows x (32 k-pairs + 4 pad) = 4608 words (K=64 fp16)
//   B  [k2][n]  stride 136: 32 k-pair rows x (128 n + 8 pad) = 4352 words
// fragment banks: A -> (4g+tig) all distinct; B -> (8tig+g) all distinct.

// ==================== fused gate/up GEMM + SiLU (fp16 mma) — R13 core ====================
// BM=128, BN=128, BK=64, 512 threads (16 warps 4x4, 32x32 warp tile).
// buffer = A 4608 + Bg 4352 + Bu 4352 = 13312 words; x2 = 104 KB.
template<bool EXPERT>
__global__ __launch_bounds__(512)
void gateup_kernel(const float* __restrict__ X, const float* __restrict__ WG,
                   const float* __restrict__ WU, int ldb) {
    extern __shared__ uint32_t smem[];
    uint32_t* bufs = smem;
    int* s_tok = (int*)(smem + 2 * 13312);

    const int tid = threadIdx.x;
    const int e  = EXPERT ? blockIdx.z : 0;
    const int ne = EXPERT ? min(g_cnt[e], CAP) : T_TOK;
    const int m0 = blockIdx.y * 128;
    if (m0 >= ne) return;
    const int n0 = blockIdx.x * 128;

    const float* Bg = EXPERT ? (WG + (size_t)e * DDIM * FDIM) : WG;
    const float* Bu = EXPERT ? (WU + (size_t)e * DDIM * FDIM) : WU;

    if (EXPERT) {
        for (int i = tid; i < 128; i += 512) {
            int m = m0 + i;
            s_tok[i] = (m < ne) ? g_slot_tok[e * CAP + m] : 0;
        }
        __syncthreads();
    }

    const float* rpA[2];
    int am[2], as_[2];
    #pragma unroll
    for (int i = 0; i < 2; i++) {
        int idx = tid + i * 512;
        am[i] = idx >> 3; as_[i] = idx & 7;
        rpA[i] = (EXPERT ? (X + (size_t)s_tok[am[i]] * DDIM)
                         : (X + (size_t)(m0 + am[i]) * DDIM)) + as_[i] * 8;
    }
    int bkp[2], bo[2], bw_[2];
    #pragma unroll
    for (int i = 0; i < 2; i++) {
        int idx = tid + i * 512;
        bkp[i] = idx >> 5;
        bo[i]  = n0 + (idx & 31) * 4;
        bw_[i] = bkp[i] * 136 + (idx & 31) * 4;
    }

    const int lane = tid & 31, warp = tid >> 5;
    const int wm = (warp >> 2) * 32, wn = (warp & 3) * 32;
    const int g = lane >> 2, tig = lane & 3;

    float cG[2][4][4] = {};
    float cU[2][4][4] = {};

    float4 hA[4], hg0, hg1, hu0, hu1;

    // ---- prologue: full tile 0 ----
    {
        uint32_t* sA  = bufs;
        uint32_t* sBg = sA + 4608;
        uint32_t* sBu = sBg + 4352;
        #pragma unroll
        for (int i = 0; i < 2; i++) {
            float4 v0 = *reinterpret_cast<const float4*>(rpA[i]);
            float4 v1 = *reinterpret_cast<const float4*>(rpA[i] + 4);
            uint4 w = { pack_h2(v0.x, v0.y), pack_h2(v0.z, v0.w),
                        pack_h2(v1.x, v1.y), pack_h2(v1.z, v1.w) };
            *reinterpret_cast<uint4*>(sA + am[i] * 36 + as_[i] * 4) = w;
        }
        #pragma unroll
        for (int i = 0; i < 2; i++) {
            const float* pg = Bg + (size_t)(2 * bkp[i]) * ldb + bo[i];
            const float* pu = Bu + (size_t)(2 * bkp[i]) * ldb + bo[i];
            float4 r0 = *reinterpret_cast<const float4*>(pg);
            float4 r1 = *reinterpret_cast<const float4*>(pg + ldb);
            uint4 wg = { pack_h2(r0.x, r1.x), pack_h2(r0.y, r1.y),
                         pack_h2(r0.z, r1.z), pack_h2(r0.w, r1.w) };
            *reinterpret_cast<uint4*>(sBg + bw_[i]) = wg;
            float4 u0 = *reinterpret_cast<const float4*>(pu);
            float4 u1 = *reinterpret_cast<const float4*>(pu + ldb);
            uint4 wu = { pack_h2(u0.x, u1.x), pack_h2(u0.y, u1.y),
                         pack_h2(u0.z, u1.z), pack_h2(u0.w, u1.w) };
            *reinterpret_cast<uint4*>(sBu + bw_[i]) = wu;
        }
    }
    __syncthreads();

    const int NK = DDIM / 64;
    for (int kt = 0; kt < NK; kt++) {
        const bool more = (kt + 1 < NK);
        const int k1 = (kt + 1) * 64;
        const uint32_t* uA  = bufs + (kt & 1) * 13312;
        const uint32_t* uBg = uA + 4608;
        const uint32_t* uBu = uBg + 4352;
        uint32_t* nA  = bufs + ((kt + 1) & 1) * 13312;
        uint32_t* nBg = nA + 4608;
        uint32_t* nBu = nBg + 4352;

        if (more) {
            #pragma unroll
            for (int i = 0; i < 2; i++) {
                hA[2 * i]     = *reinterpret_cast<const float4*>(rpA[i] + k1);
                hA[2 * i + 1] = *reinterpret_cast<const float4*>(rpA[i] + k1 + 4);
            }
            const float* pg = Bg + (size_t)(k1 + 2 * bkp[0]) * ldb + bo[0];
            const float* pu = Bu + (size_t)(k1 + 2 * bkp[0]) * ldb + bo[0];
            hg0 = *reinterpret_cast<const float4*>(pg);
            hg1 = *reinterpret_cast<const float4*>(pg + ldb);
            hu0 = *reinterpret_cast<const float4*>(pu);
            hu1 = *reinterpret_cast<const float4*>(pu + ldb);
        }

        #pragma unroll
        for (int ks = 0; ks < 2; ks++) {
            int ko = ks * 8;
            uint32_t a[2][4];
            #pragma unroll
            for (int mf = 0; mf < 2; mf++) {
                int r = wm + mf * 16 + g;
                a[mf][0] = uA[r * 36 + ko + tig];
                a[mf][1] = uA[(r + 8) * 36 + ko + tig];
                a[mf][2] = uA[r * 36 + ko + tig + 4];
                a[mf][3] = uA[(r + 8) * 36 + ko + tig + 4];
            }
            #pragma unroll
            for (int nf = 0; nf < 4; nf++) {
                int cn = wn + nf * 8 + g;
                uint32_t bg0 = uBg[(ko + tig) * 136 + cn];
                uint32_t bg1 = uBg[(ko + tig + 4) * 136 + cn];
                uint32_t bu0 = uBu[(ko + tig) * 136 + cn];
                uint32_t bu1 = uBu[(ko + tig + 4) * 136 + cn];
                mma16(cG[0][nf], a[0], bg0, bg1);
                mma16(cG[1][nf], a[1], bg0, bg1);
                mma16(cU[0][nf], a[0], bu0, bu1);
                mma16(cU[1][nf], a[1], bu0, bu1);
            }
        }

        if (more) {
            #pragma unroll
            for (int i = 0; i < 2; i++) {
                uint4 w = { pack_h2(hA[2*i].x, hA[2*i].y), pack_h2(hA[2*i].z, hA[2*i].w),
                            pack_h2(hA[2*i+1].x, hA[2*i+1].y), pack_h2(hA[2*i+1].z, hA[2*i+1].w) };
                *reinterpret_cast<uint4*>(nA + am[i] * 36 + as_[i] * 4) = w;
            }
            {
                uint4 wg = { pack_h2(hg0.x, hg1.x), pack_h2(hg0.y, hg1.y),
                             pack_h2(hg0.z, hg1.z), pack_h2(hg0.w, hg1.w) };
                *reinterpret_cast<uint4*>(nBg + bw_[0]) = wg;
                uint4 wu = { pack_h2(hu0.x, hu1.x), pack_h2(hu0.y, hu1.y),
                             pack_h2(hu0.z, hu1.z), pack_h2(hu0.w, hu1.w) };
                *reinterpret_cast<uint4*>(nBu + bw_[0]) = wu;
            }
            const float* pg = Bg + (size_t)(k1 + 2 * bkp[1]) * ldb + bo[1];
            const float* pu = Bu + (size_t)(k1 + 2 * bkp[1]) * ldb + bo[1];
            hg0 = *reinterpret_cast<const float4*>(pg);
            hg1 = *reinterpret_cast<const float4*>(pg + ldb);
            hu0 = *reinterpret_cast<const float4*>(pu);
            hu1 = *reinterpret_cast<const float4*>(pu + ldb);
        }

        #pragma unroll
        for (int ks = 2; ks < 4; ks++) {
            int ko = ks * 8;
            uint32_t a[2][4];
            #pragma unroll
            for (int mf = 0; mf < 2; mf++) {
                int r = wm + mf * 16 + g;
                a[mf][0] = uA[r * 36 + ko + tig];
                a[mf][1] = uA[(r + 8) * 36 + ko + tig];
                a[mf][2] = uA[r * 36 + ko + tig + 4];
                a[mf][3] = uA[(r + 8) * 36 + ko + tig + 4];
            }
            #pragma unroll
            for (int nf = 0; nf < 4; nf++) {
                int cn = wn + nf * 8 + g;
                uint32_t bg0 = uBg[(ko + tig) * 136 + cn];
                uint32_t bg1 = uBg[(ko + tig + 4) * 136 + cn];
                uint32_t bu0 = uBu[(ko + tig) * 136 + cn];
                uint32_t bu1 = uBu[(ko + tig + 4) * 136 + cn];
                mma16(cG[0][nf], a[0], bg0, bg1);
                mma16(cG[1][nf], a[1], bg0, bg1);
                mma16(cU[0][nf], a[0], bu0, bu1);
                mma16(cU[1][nf], a[1], bu0, bu1);
            }
        }

        if (more) {
            uint4 wg = { pack_h2(hg0.x, hg1.x), pack_h2(hg0.y, hg1.y),
                         pack_h2(hg0.z, hg1.z), pack_h2(hg0.w, hg1.w) };
            *reinterpret_cast<uint4*>(nBg + bw_[1]) = wg;
            uint4 wu = { pack_h2(hu0.x, hu1.x), pack_h2(hu0.y, hu1.y),
                         pack_h2(hu0.z, hu1.z), pack_h2(hu0.w, hu1.w) };
            *reinterpret_cast<uint4*>(nBu + bw_[1]) = wu;
        }
        __syncthreads();
    }

    __half* Hbase = EXPERT ? (g_H + (size_t)e * CAP * FDIM) : g_shared_h;
    #pragma unroll
    for (int mf = 0; mf < 2; mf++)
        #pragma unroll
        for (int nf = 0; nf < 4; nf++)
            #pragma unroll
            for (int half_ = 0; half_ < 2; half_++) {
                int row = wm + mf * 16 + g + half_ * 8;
                int col = wn + nf * 8 + 2 * tig;
                int m = m0 + row;
                if (m < ne) {
                    float g0 = cG[mf][nf][half_ * 2],     u0 = cU[mf][nf][half_ * 2];
                    float g1 = cG[mf][nf][half_ * 2 + 1], u1 = cU[mf][nf][half_ * 2 + 1];
                    float h0 = g0 / (1.f + expf(-g0)) * u0;
                    float h1 = g1 / (1.f + expf(-g1)) * u1;
                    *reinterpret_cast<uint32_t*>(Hbase + (size_t)m * FDIM + n0 + col) =
                        pack_h2(h0, h1);
                }
            }
}

// ==================== down GEMM (fp16 mma, 256 threads, 2 CTAs/SM) ====================
// BM=128, BN=128, BK=64, 256 threads (8 warps 4m x 2n, 32x64 warp tile).
// per ks: 8 A-LDS + 16 B-LDS per 16 MMA (ratio 1.5). acc = 64 regs.
// buffer = A 4608 + B 4352 = 8960 words; x2 = 70 KB -> 2 CTAs/SM.
template<bool EXPERT>
__global__ __launch_bounds__(256)
void down_kernel(const float* __restrict__ WD, float* __restrict__ out) {
    extern __shared__ uint32_t smem[];
    uint32_t* bufs = smem;
    int* s_tok = (int*)(smem + 2 * 8960);
    float* s_w = (float*)(s_tok + 128);

    const int tid = threadIdx.x;
    const int e  = EXPERT ? blockIdx.z : 0;
    const int ne = EXPERT ? min(g_cnt[e], CAP) : T_TOK;
    const int m0 = blockIdx.y * 128;
    if (m0 >= ne) return;
    const int n0 = blockIdx.x * 128;

    const float* B = EXPERT ? (WD + (size_t)e * FDIM * DDIM) : WD;
    const __half* Abase = EXPERT ? (g_H + (size_t)e * CAP * FDIM) : g_shared_h;

    if (EXPERT) {
        if (tid < 128) {
            int m = m0 + tid;
            s_tok[tid] = (m < ne) ? g_slot_tok[e * CAP + m] : 0;
            s_w[tid]   = (m < ne) ? g_slot_w[e * CAP + m] : 0.f;
        }
        __syncthreads();
    }

    // A producer (fp16 passthrough): 4 units. idx = tid + i*256 -> m = idx>>3, s = idx&7
    const __half* rpA[4];
    int am[4], as_[4];
    #pragma unroll
    for (int i = 0; i < 4; i++) {
        int idx = tid + i * 256;
        am[i] = idx >> 3; as_[i] = idx & 7;
        rpA[i] = Abase + (size_t)(m0 + am[i]) * FDIM + as_[i] * 8;
    }
    // B producer: 4 units. idx -> kp = idx>>5, ng = idx&31
    int bkp[4], bo[4], bw_[4];
    #pragma unroll
    for (int i = 0; i < 4; i++) {
        int idx = tid + i * 256;
        bkp[i] = idx >> 5;
        bo[i]  = n0 + (idx & 31) * 4;
        bw_[i] = bkp[i] * 136 + (idx & 31) * 4;
    }

    const int lane = tid & 31, warp = tid >> 5;
    const int wm = (warp >> 1) * 32, wn = (warp & 1) * 64;
    const int g = lane >> 2, tig = lane & 3;

    float c[2][8][4] = {};
    uint4 hA[4];
    float4 hb0a, hb1a, hb0b, hb1b;

    // ---- prologue: full tile 0 ----
    {
        uint32_t* sA = bufs;
        uint32_t* sB = sA + 4608;
        #pragma unroll
        for (int i = 0; i < 4; i++) {
            uint4 w = *reinterpret_cast<const uint4*>(rpA[i]);
            *reinterpret_cast<uint4*>(sA + am[i] * 36 + as_[i] * 4) = w;
        }
        #pragma unroll
        for (int i = 0; i < 4; i++) {
            const float* pb = B + (size_t)(2 * bkp[i]) * DDIM + bo[i];
            float4 r0 = *reinterpret_cast<const float4*>(pb);
            float4 r1 = *reinterpret_cast<const float4*>(pb + DDIM);
            uint4 w = { pack_h2(r0.x, r1.x), pack_h2(r0.y, r1.y),
                        pack_h2(r0.z, r1.z), pack_h2(r0.w, r1.w) };
            *reinterpret_cast<uint4*>(sB + bw_[i]) = w;
        }
    }
    __syncthreads();

    const int NK = FDIM / 64;
    for (int kt = 0; kt < NK; kt++) {
        const bool more = (kt + 1 < NK);
        const int k1 = (kt + 1) * 64;
        const uint32_t* uA = bufs + (kt & 1) * 8960;
        const uint32_t* uB = uA + 4608;
        uint32_t* nA = bufs + ((kt + 1) & 1) * 8960;
        uint32_t* nB = nA + 4608;

        // prefetch A (all 4 units) + B units 0,1 of next tile
        if (more) {
            #pragma unroll
            for (int i = 0; i < 4; i++)
                hA[i] = *reinterpret_cast<const uint4*>(rpA[i] + k1);
            const float* pb0 = B + (size_t)(k1 + 2 * bkp[0]) * DDIM + bo[0];
            hb0a = *reinterpret_cast<const float4*>(pb0);
            hb1a = *reinterpret_cast<const float4*>(pb0 + DDIM);
            const float* pb1 = B + (size_t)(k1 + 2 * bkp[1]) * DDIM + bo[1];
            hb0b = *reinterpret_cast<const float4*>(pb1);
            hb1b = *reinterpret_cast<const float4*>(pb1 + DDIM);
        }

        // compute ks = 0,1
        #pragma unroll
        for (int ks = 0; ks < 2; ks++) {
            int ko = ks * 8;
            uint32_t a[2][4];
            #pragma unroll
            for (int mf = 0; mf < 2; mf++) {
                int r = wm + mf * 16 + g;
                a[mf][0] = uA[r * 36 + ko + tig];
                a[mf][1] = uA[(r + 8) * 36 + ko + tig];
                a[mf][2] = uA[r * 36 + ko + tig + 4];
                a[mf][3] = uA[(r + 8) * 36 + ko + tig + 4];
            }
            #pragma unroll
            for (int nf = 0; nf < 8; nf++) {
                int cn = wn + nf * 8 + g;
                uint32_t b0 = uB[(ko + tig) * 136 + cn];
                uint32_t b1 = uB[(ko + tig + 4) * 136 + cn];
                mma16(c[0][nf], a[0], b0, b1);
                mma16(c[1][nf], a[1], b0, b1);
            }
        }

        // store A + B units 0,1; prefetch B units 2,3
        if (more) {
            #pragma unroll
            for (int i = 0; i < 4; i++)
                *reinterpret_cast<uint4*>(nA + am[i] * 36 + as_[i] * 4) = hA[i];
            {
                uint4 w0 = { pack_h2(hb0a.x, hb1a.x), pack_h2(hb0a.y, hb1a.y),
                             pack_h2(hb0a.z, hb1a.z), pack_h2(hb0a.w, hb1a.w) };
                *reinterpret_cast<uint4*>(nB + bw_[0]) = w0;
                uint4 w1 = { pack_h2(hb0b.x, hb1b.x), pack_h2(hb0b.y, hb1b.y),
                             pack_h2(hb0b.z, hb1b.z), pack_h2(hb0b.w, hb1b.w) };
                *reinterpret_cast<uint4*>(nB + bw_[1]) = w1;
            }
            const float* pb2 = B + (size_t)(k1 + 2 * bkp[2]) * DDIM + bo[2];
            hb0a = *reinterpret_cast<const float4*>(pb2);
            hb1a = *reinterpret_cast<const float4*>(pb2 + DDIM);
            const float* pb3 = B + (size_t)(k1 + 2 * bkp[3]) * DDIM + bo[3];
            hb0b = *reinterpret_cast<const float4*>(pb3);
            hb1b = *reinterpret_cast<const float4*>(pb3 + DDIM);
        }

        // compute ks = 2,3
        #pragma unroll
        for (int ks = 2; ks < 4; ks++) {
            int ko = ks * 8;
            uint32_t a[2][4];
            #pragma unroll
            for (int mf = 0; mf < 2; mf++) {
                int r = wm + mf * 16 + g;
                a[mf][0] = uA[r * 36 + ko + tig];
                a[mf][1] = uA[(r + 8) * 36 + ko + tig];
                a[mf][2] = uA[r * 36 + ko + tig + 4];
                a[mf][3] = uA[(r + 8) * 36 + ko + tig + 4];
            }
            #pragma unroll
            for (int nf = 0; nf < 8; nf++) {
                int cn = wn + nf * 8 + g;
                uint32_t b0 = uB[(ko + tig) * 136 + cn];
                uint32_t b1 = uB[(ko + tig + 4) * 136 + cn];
                mma16(c[0][nf], a[0], b0, b1);
                mma16(c[1][nf], a[1], b0, b1);
            }
        }

        // store B units 2,3
        if (more) {
            uint4 w2 = { pack_h2(hb0a.x, hb1a.x), pack_h2(hb0a.y, hb1a.y),
                         pack_h2(hb0a.z, hb1a.z), pack_h2(hb0a.w, hb1a.w) };
            *reinterpret_cast<uint4*>(nB + bw_[2]) = w2;
            uint4 w3 = { pack_h2(hb0b.x, hb1b.x), pack_h2(hb0b.y, hb1b.y),
                         pack_h2(hb0b.z, hb1b.z), pack_h2(hb0b.w, hb1b.w) };
            *reinterpret_cast<uint4*>(nB + bw_[3]) = w3;
        }
        __syncthreads();
    }

    #pragma unroll
    for (int mf = 0; mf < 2; mf++)
        #pragma unroll
        for (int nf = 0; nf < 8; nf++)
            #pragma unroll
            for (int half_ = 0; half_ < 2; half_++) {
                int row = wm + mf * 16 + g + half_ * 8;
                int col = wn + nf * 8 + 2 * tig;
                int m = m0 + row;
                if (m < ne) {
                    float v0 = c[mf][nf][half_ * 2];
                    float v1 = c[mf][nf][half_ * 2 + 1];
                    if (EXPERT) {
                        float w = s_w[row];
                        float* p = out + (size_t)s_tok[row] * DDIM + n0 + col;
                        asm volatile("red.global.add.v2.f32 [%0], {%1,%2};"
                                     :: "l"(p), "f"(v0 * w), "f"(v1 * w) : "memory");
                    } else {
                        float2* p = (float2*)(out + (size_t)m * DDIM + n0 + col);
                        *p = make_float2(v0, v1);
                    }
                }
            }
}

// -------------------- launch --------------------
extern "C" void kernel_launch(void* const* d_in, const int* in_sizes, int n_in,
                              void* d_out, int out_size) {
    const float* X   = (const float*)d_in[0];   // (B,S,D)
    const float* RW  = (const float*)d_in[1];   // (E,D)
    const float* WG  = (const float*)d_in[2];   // (E,D,F)
    const float* WU  = (const float*)d_in[3];   // (E,D,F)
    const float* WD  = (const float*)d_in[4];   // (E,F,D)
    const float* WSG = (const float*)d_in[5];   // (D, 2*SF)
    const float* WSD = (const float*)d_in[6];   // (SF, D)
    float* out = (float*)d_out;

    const int GUSM = (2 * 13312) * 4 + 128 * 4;   // 107008
    const int DSM  = (2 * 8960) * 4 + 128 * 8;    // 72704

    cudaFuncSetAttribute(gateup_kernel<false>, cudaFuncAttributeMaxDynamicSharedMemorySize, GUSM);
    cudaFuncSetAttribute(gateup_kernel<true>,  cudaFuncAttributeMaxDynamicSharedMemorySize, GUSM);
    cudaFuncSetAttribute(down_kernel<false>,   cudaFuncAttributeMaxDynamicSharedMemorySize, DSM);
    cudaFuncSetAttribute(down_kernel<true>,    cudaFuncAttributeMaxDynamicSharedMemorySize, DSM);

    zero_cnt_kernel<<<1, 64>>>();
    router_kernel<<<T_TOK / 32, 256>>>(X, RW);

    // shared expert gate/up: gate cols [0,768), up cols [768,1536)
    gateup_kernel<false><<<dim3(FDIM / 128, T_TOK / 128, 1), 512, GUSM>>>(X, WSG, WSG + FDIM, 2 * FDIM);
    // routed experts gate/up
    gateup_kernel<true><<<dim3(FDIM / 128, CAP / 128, NEXP), 512, GUSM>>>(X, WG, WU, FDIM);

    // shared expert down (initializes every element of out)
    down_kernel<false><<<dim3(DDIM / 128, T_TOK / 128, 1), 256, DSM>>>(WSD, out);
    // routed experts down (weighted atomic scatter)
    down_kernel<true><<<dim3(DDIM / 128, CAP / 128, NEXP), 256, DSM>>>(WD, out);
}